// round 16
// baseline (speedup 1.0000x reference)
#include <cuda_runtime.h>
#include <cuda_fp16.h>
#include <math.h>
#include <stdint.h>

#define B_ 8
#define T_ 2048
#define D_ 2048
#define H_ 128
#define M_ (B_*T_)

// q pre-scale: sqrt(128) * log2(e)  (flash uses exp2)
#define QSCALE 16.322231232383056f

// Scratch (alloc-free rules: __device__ globals)
__device__ __half g_qhi[M_*H_], g_qlo[M_*H_];
__device__ __half g_khi[M_*H_], g_klo[M_*H_];
__device__ __half g_vhi[M_*H_];
__device__ __half g_wthi[3][H_*D_];             // W^T: [n][k]
__device__ __half g_wtlo[3][H_*D_];

// ---------------------------------------------------------------------------
// helpers
// ---------------------------------------------------------------------------
__device__ __forceinline__ uint32_t smem_u32(const void* p) {
    uint32_t a;
    asm("{ .reg .u64 t; cvta.to.shared.u64 t, %1; cvt.u32.u64 %0, t; }" : "=r"(a) : "l"(p));
    return a;
}
__device__ __forceinline__ void ldmat4(uint32_t* r, uint32_t addr) {
    asm volatile("ldmatrix.sync.aligned.m8n8.x4.shared.b16 {%0,%1,%2,%3}, [%4];"
        : "=r"(r[0]), "=r"(r[1]), "=r"(r[2]), "=r"(r[3]) : "r"(addr));
}
__device__ __forceinline__ void ldmat4t(uint32_t* r, uint32_t addr) {
    asm volatile("ldmatrix.sync.aligned.m8n8.x4.trans.shared.b16 {%0,%1,%2,%3}, [%4];"
        : "=r"(r[0]), "=r"(r[1]), "=r"(r[2]), "=r"(r[3]) : "r"(addr));
}
__device__ __forceinline__ void mma16816(float* d, const uint32_t* a,
                                         uint32_t b0, uint32_t b1) {
    asm volatile(
        "mma.sync.aligned.m16n8k16.row.col.f32.f16.f16.f32 "
        "{%0,%1,%2,%3}, {%4,%5,%6,%7}, {%8,%9}, {%0,%1,%2,%3};"
        : "+f"(d[0]), "+f"(d[1]), "+f"(d[2]), "+f"(d[3])
        : "r"(a[0]), "r"(a[1]), "r"(a[2]), "r"(a[3]), "r"(b0), "r"(b1));
}
__device__ __forceinline__ uint32_t pack_f16x2(float even, float odd) {
    uint32_t r;
    asm("cvt.rn.f16x2.f32 %0, %1, %2;" : "=r"(r) : "f"(odd), "f"(even));
    return r;
}
#define CP_ASYNC16(dst, src) \
    asm volatile("cp.async.cg.shared.global [%0], [%1], 16;" :: "r"(dst), "l"(src))
#define CP_COMMIT() asm volatile("cp.async.commit_group;" ::: "memory")
#define CP_WAIT0()  asm volatile("cp.async.wait_group 0;" ::: "memory")

// ---------------------------------------------------------------------------
// W convert (unchanged from r15)
// ---------------------------------------------------------------------------
__global__ __launch_bounds__(256) void convert_w2_kernel(
    const float* __restrict__ Wq, const float* __restrict__ Wk, const float* __restrict__ Wv)
{
    extern __shared__ float cs[];
    const int w  = blockIdx.x >> 5;
    const int kt = blockIdx.x & 31;
    const float* W = (w == 0) ? Wq : (w == 1) ? Wk : Wv;
    const int t  = threadIdx.x;
    const int k0 = kt * 64;

#pragma unroll
    for (int i = 0; i < 8; i++) {
        const int idx = t + i*256;
        const int r = idx >> 5, c4 = idx & 31;
        float4 v = *(const float4*)(W + (size_t)(k0 + r) * H_ + c4*4);
        float* d = &cs[r*133 + c4*4];
        d[0] = v.x; d[1] = v.y; d[2] = v.z; d[3] = v.w;
    }
    __syncthreads();

    const int n  = t >> 1;
    const int jh = t & 1;
#pragma unroll
    for (int jb = 0; jb < 4; jb++) {
        float v[8];
#pragma unroll
        for (int u = 0; u < 8; u++)
            v[u] = cs[(jh*32 + jb*8 + u)*133 + n];
        uint32_t hw[4], lw[4];
#pragma unroll
        for (int j = 0; j < 4; j++) {
            hw[j] = pack_f16x2(v[2*j], v[2*j+1]);
            __half2 hh = *(const __half2*)&hw[j];
            lw[j] = pack_f16x2(v[2*j]   - __half2float(hh.x),
                               v[2*j+1] - __half2float(hh.y));
        }
        const size_t o = (size_t)n * D_ + k0 + jh*32 + jb*8;
        *(uint4*)(&g_wthi[w][o]) = make_uint4(hw[0], hw[1], hw[2], hw[3]);
        *(uint4*)(&g_wtlo[w][o]) = make_uint4(lw[0], lw[1], lw[2], lw[3]);
    }
}

// ---------------------------------------------------------------------------
// Projection v5: grid 148 (136 x 7 m-frags + 12 x 6).
// BALANCED warp layout: each warp owns qk cols [wid*32, wid*32+32) (3 products)
// and v cols [256+wid*16, +16) (1 product) -> 196 mma/chunk for every warp.
// ---------------------------------------------------------------------------
#define PX_RAW(buf) ((buf)*16128u)                  // 112 x 144B fp32 raw A
#define PX_AHI(buf) (32256u + (buf)*17920u)         // 112x40 f16 (stride 80B)
#define PX_ALO(buf) (PX_AHI(buf) + 8960u)
#define PX_BHI(buf) (68096u + (buf)*61440u)         // 384x40 f16 (stride 80B)
#define PX_BLO(buf) (PX_BHI(buf) + 30720u)
#define PX_SMEM     190976

template<int NF>
__device__ __forceinline__ void proj_core(
    const float* __restrict__ x, char* psm, uint32_t s0,
    int t, int lane, int wid, int m0)
{
    const __half* WT_hi = &g_wthi[0][0];
    const __half* WT_lo = &g_wtlo[0][0];

    float acc[NF][6][4];   // nt 0..3: qk cols (wid*32..), nt 4..5: v cols
#pragma unroll
    for (int mt = 0; mt < NF; mt++)
#pragma unroll
        for (int nt = 0; nt < 6; nt++)
#pragma unroll
            for (int e = 0; e < 4; e++) acc[mt][nt][e] = 0.f;

    // ldmatrix lane patterns (bytes)
    const uint32_t aoff  = (uint32_t)((((lane & 15))*40 + (lane >> 4)*8) * 2);
    const uint32_t bpat  = (uint32_t)((((lane & 7) + ((lane >> 4) & 1)*8)*40
                                      + ((lane >> 3) & 1)*8) * 2);
    const uint32_t cbq0 = (uint32_t)((wid*32      )*80);   // qk group 0 col base
    const uint32_t cbq1 = (uint32_t)((wid*32 + 16 )*80);   // qk group 1
    const uint32_t cbv  = (uint32_t)((256 + wid*16)*80);   // v group

    // prologue: issue chunk 0
    {
#pragma unroll
        for (int i = 0; i < 4; i++) {
            const int idx = t + i*256;
            if (idx < NF*128) {
                const int row = idx >> 3, c = idx & 7;
                CP_ASYNC16(s0 + PX_RAW(0) + (uint32_t)(row*144 + c*16),
                           x + (size_t)(m0 + row) * D_ + c*4);
            }
        }
#pragma unroll
        for (int i = 0; i < 6; i++) {
            const int idx = t + i*256;
            const int n = idx >> 2, c = idx & 3;
            CP_ASYNC16(s0 + PX_BHI(0) + (uint32_t)(n*80 + c*16),
                       WT_hi + (size_t)n * D_ + c*8);
            CP_ASYNC16(s0 + PX_BLO(0) + (uint32_t)(n*80 + c*16),
                       WT_lo + (size_t)n * D_ + c*8);
        }
        CP_COMMIT();
    }

    for (int ch = 0; ch < 64; ch++) {
        const int buf = ch & 1;

        CP_WAIT0();
        __syncthreads();

        // convert A raw fp32 -> f16 hi/lo
        if (t < NF*32) {
            const int row = t >> 1, half = t & 1;
            const char* rsrc = psm + PX_RAW(buf) + row*144 + half*64;
            char* dhi = psm + PX_AHI(buf) + (row*40 + half*16)*2;
            char* dlo = psm + PX_ALO(buf) + (row*40 + half*16)*2;
#pragma unroll
            for (int j = 0; j < 4; j++) {
                float4 v = *(const float4*)(rsrc + j*16);
                uint32_t h01 = pack_f16x2(v.x, v.y);
                uint32_t h23 = pack_f16x2(v.z, v.w);
                __half2 b01 = *(const __half2*)&h01;
                __half2 b23 = *(const __half2*)&h23;
                uint32_t l01 = pack_f16x2(v.x - __half2float(b01.x),
                                          v.y - __half2float(b01.y));
                uint32_t l23 = pack_f16x2(v.z - __half2float(b23.x),
                                          v.w - __half2float(b23.y));
                *(uint32_t*)(dhi + j*8)     = h01;
                *(uint32_t*)(dhi + j*8 + 4) = h23;
                *(uint32_t*)(dlo + j*8)     = l01;
                *(uint32_t*)(dlo + j*8 + 4) = l23;
            }
        }
        __syncthreads();

        // issue chunk ch+1 (interleaves with MMA)
        if (ch < 63) {
            const int nbuf = buf ^ 1;
            const int k0 = (ch + 1) * 32;
#pragma unroll
            for (int i = 0; i < 4; i++) {
                const int idx = t + i*256;
                if (idx < NF*128) {
                    const int row = idx >> 3, c = idx & 7;
                    CP_ASYNC16(s0 + PX_RAW(nbuf) + (uint32_t)(row*144 + c*16),
                               x + (size_t)(m0 + row) * D_ + k0 + c*4);
                }
            }
#pragma unroll
            for (int i = 0; i < 6; i++) {
                const int idx = t + i*256;
                const int n = idx >> 2, c = idx & 3;
                CP_ASYNC16(s0 + PX_BHI(nbuf) + (uint32_t)(n*80 + c*16),
                           WT_hi + (size_t)n * D_ + k0 + c*8);
                CP_ASYNC16(s0 + PX_BLO(nbuf) + (uint32_t)(n*80 + c*16),
                           WT_lo + (size_t)n * D_ + k0 + c*8);
            }
            CP_COMMIT();
        }

        // compute chunk ch (balanced: every warp 2 qk groups + 1 v group)
#pragma unroll
        for (int ks = 0; ks < 2; ks++) {
            const uint32_t abh = s0 + PX_AHI(buf) + aoff + ks*32;
            const uint32_t abl = s0 + PX_ALO(buf) + aoff + ks*32;
            const uint32_t bhb = s0 + PX_BHI(buf) + bpat + ks*32;
            const uint32_t blb = s0 + PX_BLO(buf) + bpat + ks*32;

            uint32_t a[NF][4], bqk[2][4];
#pragma unroll
            for (int mt = 0; mt < NF; mt++)
                ldmat4(a[mt], abh + (uint32_t)(mt*1280));

            // qk groups: hh + hl
#pragma unroll
            for (int np = 0; np < 2; np++) {
                const uint32_t cb = np ? cbq1 : cbq0;
                ldmat4(bqk[np], bhb + cb);
#pragma unroll
                for (int mt = 0; mt < NF; mt++) {
                    mma16816(acc[mt][2*np],   a[mt], bqk[np][0], bqk[np][1]);
                    mma16816(acc[mt][2*np+1], a[mt], bqk[np][2], bqk[np][3]);
                }
                uint32_t bl[4];
                ldmat4(bl, blb + cb);
#pragma unroll
                for (int mt = 0; mt < NF; mt++) {
                    mma16816(acc[mt][2*np],   a[mt], bl[0], bl[1]);
                    mma16816(acc[mt][2*np+1], a[mt], bl[2], bl[3]);
                }
            }
            // v group: hh only
            {
                uint32_t bv[4];
                ldmat4(bv, bhb + cbv);
#pragma unroll
                for (int mt = 0; mt < NF; mt++) {
                    mma16816(acc[mt][4], a[mt], bv[0], bv[1]);
                    mma16816(acc[mt][5], a[mt], bv[2], bv[3]);
                }
            }
            // lh: A = lo, qk groups (bqk kept in regs)
#pragma unroll
            for (int mt = 0; mt < NF; mt++)
                ldmat4(a[mt], abl + (uint32_t)(mt*1280));
#pragma unroll
            for (int np = 0; np < 2; np++) {
#pragma unroll
                for (int mt = 0; mt < NF; mt++) {
                    mma16816(acc[mt][2*np],   a[mt], bqk[np][0], bqk[np][1]);
                    mma16816(acc[mt][2*np+1], a[mt], bqk[np][2], bqk[np][3]);
                }
            }
        }
    }

    // epilogue
    const int dr = lane >> 2;
    const int dc = (lane & 3) * 2;
#pragma unroll
    for (int mt = 0; mt < NF; mt++) {
        const int row = m0 + mt*16 + dr;
#pragma unroll
        for (int nt = 0; nt < 6; nt++) {
            if (nt < 4) {
                const int cg  = wid*32 + nt*8 + dc;   // 0..255
                const int w   = cg >> 7;              // 0=q, 1=k
                const int col = cg & 127;
                __half* ohi = (w == 0) ? g_qhi : g_khi;
                __half* olo = (w == 0) ? g_qlo : g_klo;
                const float sc = (w == 0) ? QSCALE : 1.0f;
#pragma unroll
                for (int half = 0; half < 2; half++) {
                    const int rr = row + half*8;
                    float v0 = acc[mt][nt][half*2 + 0] * sc;
                    float v1 = acc[mt][nt][half*2 + 1] * sc;
                    uint32_t h = pack_f16x2(v0, v1);
                    __half2 bh2 = *(const __half2*)&h;
                    uint32_t l = pack_f16x2(v0 - __half2float(bh2.x),
                                            v1 - __half2float(bh2.y));
                    *(uint32_t*)(ohi + (size_t)rr * H_ + col) = h;
                    *(uint32_t*)(olo + (size_t)rr * H_ + col) = l;
                }
            } else {
                const int col = wid*16 + (nt-4)*8 + dc;   // v col 0..127
#pragma unroll
                for (int half = 0; half < 2; half++) {
                    const int rr = row + half*8;
                    uint32_t h = pack_f16x2(acc[mt][nt][half*2 + 0],
                                            acc[mt][nt][half*2 + 1]);
                    *(uint32_t*)(g_vhi + (size_t)rr * H_ + col) = h;
                }
            }
        }
    }
}

__global__ __launch_bounds__(256, 1) void proj_hmma5_kernel(const float* __restrict__ x)
{
    extern __shared__ char psm[];
    const uint32_t s0 = smem_u32(psm);
    const int t    = threadIdx.x;
    const int lane = t & 31;
    const int wid  = t >> 5;
    const int bid  = blockIdx.x;

    if (bid < 136) {
        proj_core<7>(x, psm, s0, t, lane, wid, bid*112);
    } else {
        proj_core<6>(x, psm, s0, t, lane, wid, 15232 + (bid-136)*96);
    }
}

// ---------------------------------------------------------------------------
// Flash attention v6 — exp2 domain (log2e pre-folded into q scale).
// ---------------------------------------------------------------------------
#define FSTR 136
#define FQH  (64*FSTR)
#define FGRP (5*FQH)
#define FSMEM (2*FGRP*2)

__global__ __launch_bounds__(256) void flash6_kernel(float* __restrict__ out)
{
    extern __shared__ __half fsm[];
    const int t    = threadIdx.x;
    const int g    = t >> 7;
    const int gt   = t & 127;
    const int warp = gt >> 5;
    const int lane = t & 31;
    const int b    = blockIdx.y;
    const int p    = blockIdx.x;
    const int qb   = g ? p : (31 - p);
    const int q0   = qb * 64;
    const size_t base = (size_t)b * T_ * H_;

    __half* sQh = fsm + g*FGRP;
    __half* sQl = sQh + FQH;
    __half* sKh = sQl + FQH;
    __half* sKl = sKh + FQH;
    __half* sVh = sKl + FQH;
    const uint32_t aQh = smem_u32(sQh), aQl = smem_u32(sQl);
    const uint32_t aKh = smem_u32(sKh), aKl = smem_u32(sKl);
    const uint32_t aVh = smem_u32(sVh);

#pragma unroll
    for (int i = 0; i < 8; i++) {
        const int idx = gt + i*128;
        const int row = idx >> 4, c = idx & 15;
        const size_t go = base + (size_t)(q0 + row)*H_ + c*8;
        *(uint4*)(sQh + row*FSTR + c*8) = *(const uint4*)(g_qhi + go);
        *(uint4*)(sQl + row*FSTR + c*8) = *(const uint4*)(g_qlo + go);
    }

    float o[16][4];
#pragma unroll
    for (int nt = 0; nt < 16; nt++)
#pragma unroll
        for (int e = 0; e < 4; e++) o[nt][e] = 0.f;
    float m0r = -1e30f, m1r = -1e30f, l0r = 0.f, l1r = 0.f;

    const uint32_t aoff = (uint32_t)(((warp*16 + (lane & 15))*FSTR + (lane >> 4)*8) * 2);
    const uint32_t boff = (uint32_t)((((lane & 7) + ((lane >> 4) & 1)*8)*FSTR
                                      + ((lane >> 3) & 1)*8) * 2);
    const uint32_t voff4 = (uint32_t)(((lane & 15)*FSTR)*2 + (lane >> 4)*16);

    const int r0 = warp*16 + (lane >> 2);

    for (int kb = 0; kb <= qb; kb++) {
        const int k0 = kb * 64;
        asm volatile("bar.sync %0, %1;" :: "r"(g+1), "r"(128) : "memory");

#pragma unroll
        for (int i = 0; i < 8; i++) {
            const int idx = gt + i*128;
            const int row = idx >> 4, c = idx & 15;
            const size_t go = base + (size_t)(k0 + row)*H_ + c*8;
            *(uint4*)(sKh + row*FSTR + c*8) = *(const uint4*)(g_khi + go);
            *(uint4*)(sKl + row*FSTR + c*8) = *(const uint4*)(g_klo + go);
            *(uint4*)(sVh + row*FSTR + c*8) = *(const uint4*)(g_vhi + go);
        }
        asm volatile("bar.sync %0, %1;" :: "r"(g+1), "r"(128) : "memory");

        // ---- S = Q K^T : hh + hl + lh (logits in log2 domain) ----
        float s[8][4];
#pragma unroll
        for (int nt = 0; nt < 8; nt++)
#pragma unroll
            for (int e = 0; e < 4; e++) s[nt][e] = 0.f;

#pragma unroll
        for (int kc = 0; kc < 8; kc++) {
            uint32_t aH[4], aL[4];
            ldmat4(aH, aQh + aoff + kc*32);
            ldmat4(aL, aQl + aoff + kc*32);
#pragma unroll
            for (int ntp = 0; ntp < 4; ntp++) {
                uint32_t bH[4], bL[4];
                const uint32_t bo = boff + (uint32_t)(ntp*(16*FSTR*2)) + kc*32;
                ldmat4(bH, aKh + bo);
                ldmat4(bL, aKl + bo);
#pragma unroll
                for (int h = 0; h < 2; h++) {
                    const int nt = ntp*2 + h;
                    mma16816(s[nt], aH, bH[2*h], bH[2*h+1]);
                    mma16816(s[nt], aH, bL[2*h], bL[2*h+1]);
                    mma16816(s[nt], aL, bH[2*h], bH[2*h+1]);
                }
            }
        }

        if (kb == qb) {
#pragma unroll
            for (int nt = 0; nt < 8; nt++) {
                const int c0 = nt*8 + 2*(lane & 3);
                if (c0     > r0)     s[nt][0] = -1e9f;
                if (c0 + 1 > r0)     s[nt][1] = -1e9f;
                if (c0     > r0 + 8) s[nt][2] = -1e9f;
                if (c0 + 1 > r0 + 8) s[nt][3] = -1e9f;
            }
        }

        float mx0 = -1e30f, mx1 = -1e30f;
#pragma unroll
        for (int nt = 0; nt < 8; nt++) {
            mx0 = fmaxf(mx0, fmaxf(s[nt][0], s[nt][1]));
            mx1 = fmaxf(mx1, fmaxf(s[nt][2], s[nt][3]));
        }
        mx0 = fmaxf(mx0, __shfl_xor_sync(0xffffffffu, mx0, 1));
        mx0 = fmaxf(mx0, __shfl_xor_sync(0xffffffffu, mx0, 2));
        mx1 = fmaxf(mx1, __shfl_xor_sync(0xffffffffu, mx1, 1));
        mx1 = fmaxf(mx1, __shfl_xor_sync(0xffffffffu, mx1, 2));

        const float mn0 = fmaxf(m0r, mx0);
        const float mn1 = fmaxf(m1r, mx1);
        const float sc0 = exp2f(m0r - mn0);
        const float sc1 = exp2f(m1r - mn1);
        m0r = mn0; m1r = mn1;

        float rs0 = 0.f, rs1 = 0.f;
#pragma unroll
        for (int nt = 0; nt < 8; nt++) {
            s[nt][0] = exp2f(s[nt][0] - mn0); rs0 += s[nt][0];
            s[nt][1] = exp2f(s[nt][1] - mn0); rs0 += s[nt][1];
            s[nt][2] = exp2f(s[nt][2] - mn1); rs1 += s[nt][2];
            s[nt][3] = exp2f(s[nt][3] - mn1); rs1 += s[nt][3];
        }
        rs0 += __shfl_xor_sync(0xffffffffu, rs0, 1);
        rs0 += __shfl_xor_sync(0xffffffffu, rs0, 2);
        rs1 += __shfl_xor_sync(0xffffffffu, rs1, 1);
        rs1 += __shfl_xor_sync(0xffffffffu, rs1, 2);
        l0r = l0r*sc0 + rs0;
        l1r = l1r*sc1 + rs1;

#pragma unroll
        for (int nt = 0; nt < 16; nt++) {
            o[nt][0] *= sc0; o[nt][1] *= sc0;
            o[nt][2] *= sc1; o[nt][3] *= sc1;
        }

        // ---- O += P V : Ph*Vh ----
#pragma unroll
        for (int kc4 = 0; kc4 < 4; kc4++) {
            uint32_t aPh[4];
#pragma unroll
            for (int hh = 0; hh < 2; hh++) {
                aPh[2*hh]   = pack_f16x2(s[2*kc4+hh][0], s[2*kc4+hh][1]);
                aPh[2*hh+1] = pack_f16x2(s[2*kc4+hh][2], s[2*kc4+hh][3]);
            }
#pragma unroll
            for (int ntp = 0; ntp < 8; ntp++) {
                uint32_t vH[4];
                const uint32_t vo = voff4 + (uint32_t)(kc4*(16*FSTR*2)) + ntp*32;
                ldmat4t(vH, aVh + vo);
                mma16816(o[2*ntp],   aPh, vH[0], vH[1]);
                mma16816(o[2*ntp+1], aPh, vH[2], vH[3]);
            }
        }
    }

    const float li0 = 1.f / l0r, li1 = 1.f / l1r;
    const int rg = q0 + r0;
    const int cb = 2*(lane & 3);
#pragma unroll
    for (int nt = 0; nt < 16; nt++) {
        const int col = nt*8 + cb;
        *(float2*)&out[base + (size_t)rg*H_ + col] =
            make_float2(o[nt][0]*li0, o[nt][1]*li0);
        *(float2*)&out[base + (size_t)(rg+8)*H_ + col] =
            make_float2(o[nt][2]*li1, o[nt][3]*li1);
    }
}

// ---------------------------------------------------------------------------
extern "C" void kernel_launch(void* const* d_in, const int* in_sizes, int n_in,
                              void* d_out, int out_size)
{
    (void)in_sizes; (void)n_in; (void)out_size;
    const float* x  = (const float*)d_in[0];
    const float* Wq = (const float*)d_in[1];
    const float* Wk = (const float*)d_in[2];
    const float* Wv = (const float*)d_in[3];
    float* out = (float*)d_out;

    convert_w2_kernel<<<96, 256, 64*133*4>>>(Wq, Wk, Wv);

    cudaFuncSetAttribute(proj_hmma5_kernel,
                         cudaFuncAttributeMaxDynamicSharedMemorySize, PX_SMEM);
    proj_hmma5_kernel<<<148, 256, PX_SMEM>>>(x);

    cudaFuncSetAttribute(flash6_kernel,
                         cudaFuncAttributeMaxDynamicSharedMemorySize, FSMEM);
    flash6_kernel<<<dim3(16, B_), 256, FSMEM>>>(out);
}

// round 17
// speedup vs baseline: 1.5457x; 1.5457x over previous
#include <cuda_runtime.h>
#include <cuda_fp16.h>
#include <math.h>
#include <stdint.h>

#define B_ 8
#define T_ 2048
#define D_ 2048
#define H_ 128
#define M_ (B_*T_)

// q pre-scale: sqrt(128) * log2(e)  (flash uses raw EX2)
#define QSCALE 16.322231232383056f

// Scratch (alloc-free rules: __device__ globals)
__device__ __half g_qhi[M_*H_], g_qlo[M_*H_];
__device__ __half g_khi[M_*H_], g_klo[M_*H_];
__device__ __half g_vhi[M_*H_];
__device__ __half g_wthi[3][H_*D_];             // W^T: [n][k]
__device__ __half g_wtlo[3][H_*D_];

// ---------------------------------------------------------------------------
// helpers
// ---------------------------------------------------------------------------
__device__ __forceinline__ uint32_t smem_u32(const void* p) {
    uint32_t a;
    asm("{ .reg .u64 t; cvta.to.shared.u64 t, %1; cvt.u32.u64 %0, t; }" : "=r"(a) : "l"(p));
    return a;
}
// raw MUFU.EX2 (2^x), single instruction
__device__ __forceinline__ float ex2(float x) {
    float y;
    asm("ex2.approx.ftz.f32 %0, %1;" : "=f"(y) : "f"(x));
    return y;
}
__device__ __forceinline__ void ldmat4(uint32_t* r, uint32_t addr) {
    asm volatile("ldmatrix.sync.aligned.m8n8.x4.shared.b16 {%0,%1,%2,%3}, [%4];"
        : "=r"(r[0]), "=r"(r[1]), "=r"(r[2]), "=r"(r[3]) : "r"(addr));
}
__device__ __forceinline__ void ldmat4t(uint32_t* r, uint32_t addr) {
    asm volatile("ldmatrix.sync.aligned.m8n8.x4.trans.shared.b16 {%0,%1,%2,%3}, [%4];"
        : "=r"(r[0]), "=r"(r[1]), "=r"(r[2]), "=r"(r[3]) : "r"(addr));
}
__device__ __forceinline__ void mma16816(float* d, const uint32_t* a,
                                         uint32_t b0, uint32_t b1) {
    asm volatile(
        "mma.sync.aligned.m16n8k16.row.col.f32.f16.f16.f32 "
        "{%0,%1,%2,%3}, {%4,%5,%6,%7}, {%8,%9}, {%0,%1,%2,%3};"
        : "+f"(d[0]), "+f"(d[1]), "+f"(d[2]), "+f"(d[3])
        : "r"(a[0]), "r"(a[1]), "r"(a[2]), "r"(a[3]), "r"(b0), "r"(b1));
}
__device__ __forceinline__ uint32_t pack_f16x2(float even, float odd) {
    uint32_t r;
    asm("cvt.rn.f16x2.f32 %0, %1, %2;" : "=r"(r) : "f"(odd), "f"(even));
    return r;
}
#define CP_ASYNC16(dst, src) \
    asm volatile("cp.async.cg.shared.global [%0], [%1], 16;" :: "r"(dst), "l"(src))
#define CP_COMMIT() asm volatile("cp.async.commit_group;" ::: "memory")
#define CP_WAIT0()  asm volatile("cp.async.wait_group 0;" ::: "memory")

// ---------------------------------------------------------------------------
// W convert (r15 version)
// ---------------------------------------------------------------------------
__global__ __launch_bounds__(256) void convert_w2_kernel(
    const float* __restrict__ Wq, const float* __restrict__ Wk, const float* __restrict__ Wv)
{
    extern __shared__ float cs[];
    const int w  = blockIdx.x >> 5;
    const int kt = blockIdx.x & 31;
    const float* W = (w == 0) ? Wq : (w == 1) ? Wk : Wv;
    const int t  = threadIdx.x;
    const int k0 = kt * 64;

#pragma unroll
    for (int i = 0; i < 8; i++) {
        const int idx = t + i*256;
        const int r = idx >> 5, c4 = idx & 31;
        float4 v = *(const float4*)(W + (size_t)(k0 + r) * H_ + c4*4);
        float* d = &cs[r*133 + c4*4];
        d[0] = v.x; d[1] = v.y; d[2] = v.z; d[3] = v.w;
    }
    __syncthreads();

    const int n  = t >> 1;
    const int jh = t & 1;
#pragma unroll
    for (int jb = 0; jb < 4; jb++) {
        float v[8];
#pragma unroll
        for (int u = 0; u < 8; u++)
            v[u] = cs[(jh*32 + jb*8 + u)*133 + n];
        uint32_t hw[4], lw[4];
#pragma unroll
        for (int j = 0; j < 4; j++) {
            hw[j] = pack_f16x2(v[2*j], v[2*j+1]);
            __half2 hh = *(const __half2*)&hw[j];
            lw[j] = pack_f16x2(v[2*j]   - __half2float(hh.x),
                               v[2*j+1] - __half2float(hh.y));
        }
        const size_t o = (size_t)n * D_ + k0 + jh*32 + jb*8;
        *(uint4*)(&g_wthi[w][o]) = make_uint4(hw[0], hw[1], hw[2], hw[3]);
        *(uint4*)(&g_wtlo[w][o]) = make_uint4(lw[0], lw[1], lw[2], lw[3]);
    }
}

// ---------------------------------------------------------------------------
// Projection v5 (balanced warp layout, r16): each warp 2 qk groups + 1 v group
// = 196 mma/chunk for every warp.
// ---------------------------------------------------------------------------
#define PX_RAW(buf) ((buf)*16128u)
#define PX_AHI(buf) (32256u + (buf)*17920u)
#define PX_ALO(buf) (PX_AHI(buf) + 8960u)
#define PX_BHI(buf) (68096u + (buf)*61440u)
#define PX_BLO(buf) (PX_BHI(buf) + 30720u)
#define PX_SMEM     190976

template<int NF>
__device__ __forceinline__ void proj_core(
    const float* __restrict__ x, char* psm, uint32_t s0,
    int t, int lane, int wid, int m0)
{
    const __half* WT_hi = &g_wthi[0][0];
    const __half* WT_lo = &g_wtlo[0][0];

    float acc[NF][6][4];
#pragma unroll
    for (int mt = 0; mt < NF; mt++)
#pragma unroll
        for (int nt = 0; nt < 6; nt++)
#pragma unroll
            for (int e = 0; e < 4; e++) acc[mt][nt][e] = 0.f;

    const uint32_t aoff  = (uint32_t)((((lane & 15))*40 + (lane >> 4)*8) * 2);
    const uint32_t bpat  = (uint32_t)((((lane & 7) + ((lane >> 4) & 1)*8)*40
                                      + ((lane >> 3) & 1)*8) * 2);
    const uint32_t cbq0 = (uint32_t)((wid*32      )*80);
    const uint32_t cbq1 = (uint32_t)((wid*32 + 16 )*80);
    const uint32_t cbv  = (uint32_t)((256 + wid*16)*80);

    // prologue: issue chunk 0
    {
#pragma unroll
        for (int i = 0; i < 4; i++) {
            const int idx = t + i*256;
            if (idx < NF*128) {
                const int row = idx >> 3, c = idx & 7;
                CP_ASYNC16(s0 + PX_RAW(0) + (uint32_t)(row*144 + c*16),
                           x + (size_t)(m0 + row) * D_ + c*4);
            }
        }
#pragma unroll
        for (int i = 0; i < 6; i++) {
            const int idx = t + i*256;
            const int n = idx >> 2, c = idx & 3;
            CP_ASYNC16(s0 + PX_BHI(0) + (uint32_t)(n*80 + c*16),
                       WT_hi + (size_t)n * D_ + c*8);
            CP_ASYNC16(s0 + PX_BLO(0) + (uint32_t)(n*80 + c*16),
                       WT_lo + (size_t)n * D_ + c*8);
        }
        CP_COMMIT();
    }

    for (int ch = 0; ch < 64; ch++) {
        const int buf = ch & 1;

        CP_WAIT0();
        __syncthreads();

        if (t < NF*32) {
            const int row = t >> 1, half = t & 1;
            const char* rsrc = psm + PX_RAW(buf) + row*144 + half*64;
            char* dhi = psm + PX_AHI(buf) + (row*40 + half*16)*2;
            char* dlo = psm + PX_ALO(buf) + (row*40 + half*16)*2;
#pragma unroll
            for (int j = 0; j < 4; j++) {
                float4 v = *(const float4*)(rsrc + j*16);
                uint32_t h01 = pack_f16x2(v.x, v.y);
                uint32_t h23 = pack_f16x2(v.z, v.w);
                __half2 b01 = *(const __half2*)&h01;
                __half2 b23 = *(const __half2*)&h23;
                uint32_t l01 = pack_f16x2(v.x - __half2float(b01.x),
                                          v.y - __half2float(b01.y));
                uint32_t l23 = pack_f16x2(v.z - __half2float(b23.x),
                                          v.w - __half2float(b23.y));
                *(uint32_t*)(dhi + j*8)     = h01;
                *(uint32_t*)(dhi + j*8 + 4) = h23;
                *(uint32_t*)(dlo + j*8)     = l01;
                *(uint32_t*)(dlo + j*8 + 4) = l23;
            }
        }
        __syncthreads();

        if (ch < 63) {
            const int nbuf = buf ^ 1;
            const int k0 = (ch + 1) * 32;
#pragma unroll
            for (int i = 0; i < 4; i++) {
                const int idx = t + i*256;
                if (idx < NF*128) {
                    const int row = idx >> 3, c = idx & 7;
                    CP_ASYNC16(s0 + PX_RAW(nbuf) + (uint32_t)(row*144 + c*16),
                               x + (size_t)(m0 + row) * D_ + k0 + c*4);
                }
            }
#pragma unroll
            for (int i = 0; i < 6; i++) {
                const int idx = t + i*256;
                const int n = idx >> 2, c = idx & 3;
                CP_ASYNC16(s0 + PX_BHI(nbuf) + (uint32_t)(n*80 + c*16),
                           WT_hi + (size_t)n * D_ + k0 + c*8);
                CP_ASYNC16(s0 + PX_BLO(nbuf) + (uint32_t)(n*80 + c*16),
                           WT_lo + (size_t)n * D_ + k0 + c*8);
            }
            CP_COMMIT();
        }

#pragma unroll
        for (int ks = 0; ks < 2; ks++) {
            const uint32_t abh = s0 + PX_AHI(buf) + aoff + ks*32;
            const uint32_t abl = s0 + PX_ALO(buf) + aoff + ks*32;
            const uint32_t bhb = s0 + PX_BHI(buf) + bpat + ks*32;
            const uint32_t blb = s0 + PX_BLO(buf) + bpat + ks*32;

            uint32_t a[NF][4], bqk[2][4];
#pragma unroll
            for (int mt = 0; mt < NF; mt++)
                ldmat4(a[mt], abh + (uint32_t)(mt*1280));

#pragma unroll
            for (int np = 0; np < 2; np++) {
                const uint32_t cb = np ? cbq1 : cbq0;
                ldmat4(bqk[np], bhb + cb);
#pragma unroll
                for (int mt = 0; mt < NF; mt++) {
                    mma16816(acc[mt][2*np],   a[mt], bqk[np][0], bqk[np][1]);
                    mma16816(acc[mt][2*np+1], a[mt], bqk[np][2], bqk[np][3]);
                }
                uint32_t bl[4];
                ldmat4(bl, blb + cb);
#pragma unroll
                for (int mt = 0; mt < NF; mt++) {
                    mma16816(acc[mt][2*np],   a[mt], bl[0], bl[1]);
                    mma16816(acc[mt][2*np+1], a[mt], bl[2], bl[3]);
                }
            }
            {
                uint32_t bv[4];
                ldmat4(bv, bhb + cbv);
#pragma unroll
                for (int mt = 0; mt < NF; mt++) {
                    mma16816(acc[mt][4], a[mt], bv[0], bv[1]);
                    mma16816(acc[mt][5], a[mt], bv[2], bv[3]);
                }
            }
#pragma unroll
            for (int mt = 0; mt < NF; mt++)
                ldmat4(a[mt], abl + (uint32_t)(mt*1280));
#pragma unroll
            for (int np = 0; np < 2; np++) {
#pragma unroll
                for (int mt = 0; mt < NF; mt++) {
                    mma16816(acc[mt][2*np],   a[mt], bqk[np][0], bqk[np][1]);
                    mma16816(acc[mt][2*np+1], a[mt], bqk[np][2], bqk[np][3]);
                }
            }
        }
    }

    // epilogue
    const int dr = lane >> 2;
    const int dc = (lane & 3) * 2;
#pragma unroll
    for (int mt = 0; mt < NF; mt++) {
        const int row = m0 + mt*16 + dr;
#pragma unroll
        for (int nt = 0; nt < 6; nt++) {
            if (nt < 4) {
                const int cg  = wid*32 + nt*8 + dc;
                const int w   = cg >> 7;
                const int col = cg & 127;
                __half* ohi = (w == 0) ? g_qhi : g_khi;
                __half* olo = (w == 0) ? g_qlo : g_klo;
                const float sc = (w == 0) ? QSCALE : 1.0f;
#pragma unroll
                for (int half = 0; half < 2; half++) {
                    const int rr = row + half*8;
                    float v0 = acc[mt][nt][half*2 + 0] * sc;
                    float v1 = acc[mt][nt][half*2 + 1] * sc;
                    uint32_t h = pack_f16x2(v0, v1);
                    __half2 bh2 = *(const __half2*)&h;
                    uint32_t l = pack_f16x2(v0 - __half2float(bh2.x),
                                            v1 - __half2float(bh2.y));
                    *(uint32_t*)(ohi + (size_t)rr * H_ + col) = h;
                    *(uint32_t*)(olo + (size_t)rr * H_ + col) = l;
                }
            } else {
                const int col = wid*16 + (nt-4)*8 + dc;
#pragma unroll
                for (int half = 0; half < 2; half++) {
                    const int rr = row + half*8;
                    uint32_t h = pack_f16x2(acc[mt][nt][half*2 + 0],
                                            acc[mt][nt][half*2 + 1]);
                    *(uint32_t*)(g_vhi + (size_t)rr * H_ + col) = h;
                }
            }
        }
    }
}

__global__ __launch_bounds__(256, 1) void proj_hmma5_kernel(const float* __restrict__ x)
{
    extern __shared__ char psm[];
    const uint32_t s0 = smem_u32(psm);
    const int t    = threadIdx.x;
    const int lane = t & 31;
    const int wid  = t >> 5;
    const int bid  = blockIdx.x;

    if (bid < 136) {
        proj_core<7>(x, psm, s0, t, lane, wid, bid*112);
    } else {
        proj_core<6>(x, psm, s0, t, lane, wid, 15232 + (bid-136)*96);
    }
}

// ---------------------------------------------------------------------------
// Flash attention v6.1 — exp2 domain via raw MUFU.EX2 (ex2.approx.ftz).
// ---------------------------------------------------------------------------
#define FSTR 136
#define FQH  (64*FSTR)
#define FGRP (5*FQH)
#define FSMEM (2*FGRP*2)

__global__ __launch_bounds__(256) void flash6_kernel(float* __restrict__ out)
{
    extern __shared__ __half fsm[];
    const int t    = threadIdx.x;
    const int g    = t >> 7;
    const int gt   = t & 127;
    const int warp = gt >> 5;
    const int lane = t & 31;
    const int b    = blockIdx.y;
    const int p    = blockIdx.x;
    const int qb   = g ? p : (31 - p);
    const int q0   = qb * 64;
    const size_t base = (size_t)b * T_ * H_;

    __half* sQh = fsm + g*FGRP;
    __half* sQl = sQh + FQH;
    __half* sKh = sQl + FQH;
    __half* sKl = sKh + FQH;
    __half* sVh = sKl + FQH;
    const uint32_t aQh = smem_u32(sQh), aQl = smem_u32(sQl);
    const uint32_t aKh = smem_u32(sKh), aKl = smem_u32(sKl);
    const uint32_t aVh = smem_u32(sVh);

#pragma unroll
    for (int i = 0; i < 8; i++) {
        const int idx = gt + i*128;
        const int row = idx >> 4, c = idx & 15;
        const size_t go = base + (size_t)(q0 + row)*H_ + c*8;
        *(uint4*)(sQh + row*FSTR + c*8) = *(const uint4*)(g_qhi + go);
        *(uint4*)(sQl + row*FSTR + c*8) = *(const uint4*)(g_qlo + go);
    }

    float o[16][4];
#pragma unroll
    for (int nt = 0; nt < 16; nt++)
#pragma unroll
        for (int e = 0; e < 4; e++) o[nt][e] = 0.f;
    float m0r = -1e30f, m1r = -1e30f, l0r = 0.f, l1r = 0.f;

    const uint32_t aoff = (uint32_t)(((warp*16 + (lane & 15))*FSTR + (lane >> 4)*8) * 2);
    const uint32_t boff = (uint32_t)((((lane & 7) + ((lane >> 4) & 1)*8)*FSTR
                                      + ((lane >> 3) & 1)*8) * 2);
    const uint32_t voff4 = (uint32_t)(((lane & 15)*FSTR)*2 + (lane >> 4)*16);

    const int r0 = warp*16 + (lane >> 2);

    for (int kb = 0; kb <= qb; kb++) {
        const int k0 = kb * 64;
        asm volatile("bar.sync %0, %1;" :: "r"(g+1), "r"(128) : "memory");

#pragma unroll
        for (int i = 0; i < 8; i++) {
            const int idx = gt + i*128;
            const int row = idx >> 4, c = idx & 15;
            const size_t go = base + (size_t)(k0 + row)*H_ + c*8;
            *(uint4*)(sKh + row*FSTR + c*8) = *(const uint4*)(g_khi + go);
            *(uint4*)(sKl + row*FSTR + c*8) = *(const uint4*)(g_klo + go);
            *(uint4*)(sVh + row*FSTR + c*8) = *(const uint4*)(g_vhi + go);
        }
        asm volatile("bar.sync %0, %1;" :: "r"(g+1), "r"(128) : "memory");

        // ---- S = Q K^T : hh + hl + lh (logits in log2 domain) ----
        float s[8][4];
#pragma unroll
        for (int nt = 0; nt < 8; nt++)
#pragma unroll
            for (int e = 0; e < 4; e++) s[nt][e] = 0.f;

#pragma unroll
        for (int kc = 0; kc < 8; kc++) {
            uint32_t aH[4], aL[4];
            ldmat4(aH, aQh + aoff + kc*32);
            ldmat4(aL, aQl + aoff + kc*32);
#pragma unroll
            for (int ntp = 0; ntp < 4; ntp++) {
                uint32_t bH[4], bL[4];
                const uint32_t bo = boff + (uint32_t)(ntp*(16*FSTR*2)) + kc*32;
                ldmat4(bH, aKh + bo);
                ldmat4(bL, aKl + bo);
#pragma unroll
                for (int h = 0; h < 2; h++) {
                    const int nt = ntp*2 + h;
                    mma16816(s[nt], aH, bH[2*h], bH[2*h+1]);
                    mma16816(s[nt], aH, bL[2*h], bL[2*h+1]);
                    mma16816(s[nt], aL, bH[2*h], bH[2*h+1]);
                }
            }
        }

        if (kb == qb) {
#pragma unroll
            for (int nt = 0; nt < 8; nt++) {
                const int c0 = nt*8 + 2*(lane & 3);
                if (c0     > r0)     s[nt][0] = -1e9f;
                if (c0 + 1 > r0)     s[nt][1] = -1e9f;
                if (c0     > r0 + 8) s[nt][2] = -1e9f;
                if (c0 + 1 > r0 + 8) s[nt][3] = -1e9f;
            }
        }

        float mx0 = -1e30f, mx1 = -1e30f;
#pragma unroll
        for (int nt = 0; nt < 8; nt++) {
            mx0 = fmaxf(mx0, fmaxf(s[nt][0], s[nt][1]));
            mx1 = fmaxf(mx1, fmaxf(s[nt][2], s[nt][3]));
        }
        mx0 = fmaxf(mx0, __shfl_xor_sync(0xffffffffu, mx0, 1));
        mx0 = fmaxf(mx0, __shfl_xor_sync(0xffffffffu, mx0, 2));
        mx1 = fmaxf(mx1, __shfl_xor_sync(0xffffffffu, mx1, 1));
        mx1 = fmaxf(mx1, __shfl_xor_sync(0xffffffffu, mx1, 2));

        const float mn0 = fmaxf(m0r, mx0);
        const float mn1 = fmaxf(m1r, mx1);
        const float sc0 = ex2(m0r - mn0);
        const float sc1 = ex2(m1r - mn1);
        m0r = mn0; m1r = mn1;

        float rs0 = 0.f, rs1 = 0.f;
#pragma unroll
        for (int nt = 0; nt < 8; nt++) {
            s[nt][0] = ex2(s[nt][0] - mn0); rs0 += s[nt][0];
            s[nt][1] = ex2(s[nt][1] - mn0); rs0 += s[nt][1];
            s[nt][2] = ex2(s[nt][2] - mn1); rs1 += s[nt][2];
            s[nt][3] = ex2(s[nt][3] - mn1); rs1 += s[nt][3];
        }
        rs0 += __shfl_xor_sync(0xffffffffu, rs0, 1);
        rs0 += __shfl_xor_sync(0xffffffffu, rs0, 2);
        rs1 += __shfl_xor_sync(0xffffffffu, rs1, 1);
        rs1 += __shfl_xor_sync(0xffffffffu, rs1, 2);
        l0r = l0r*sc0 + rs0;
        l1r = l1r*sc1 + rs1;

#pragma unroll
        for (int nt = 0; nt < 16; nt++) {
            o[nt][0] *= sc0; o[nt][1] *= sc0;
            o[nt][2] *= sc1; o[nt][3] *= sc1;
        }

        // ---- O += P V : Ph*Vh ----
#pragma unroll
        for (int kc4 = 0; kc4 < 4; kc4++) {
            uint32_t aPh[4];
#pragma unroll
            for (int hh = 0; hh < 2; hh++) {
                aPh[2*hh]   = pack_f16x2(s[2*kc4+hh][0], s[2*kc4+hh][1]);
                aPh[2*hh+1] = pack_f16x2(s[2*kc4+hh][2], s[2*kc4+hh][3]);
            }
#pragma unroll
            for (int ntp = 0; ntp < 8; ntp++) {
                uint32_t vH[4];
                const uint32_t vo = voff4 + (uint32_t)(kc4*(16*FSTR*2)) + ntp*32;
                ldmat4t(vH, aVh + vo);
                mma16816(o[2*ntp],   aPh, vH[0], vH[1]);
                mma16816(o[2*ntp+1], aPh, vH[2], vH[3]);
            }
        }
    }

    const float li0 = 1.f / l0r, li1 = 1.f / l1r;
    const int rg = q0 + r0;
    const int cb = 2*(lane & 3);
#pragma unroll
    for (int nt = 0; nt < 16; nt++) {
        const int col = nt*8 + cb;
        *(float2*)&out[base + (size_t)rg*H_ + col] =
            make_float2(o[nt][0]*li0, o[nt][1]*li0);
        *(float2*)&out[base + (size_t)(rg+8)*H_ + col] =
            make_float2(o[nt][2]*li1, o[nt][3]*li1);
    }
}

// ---------------------------------------------------------------------------
extern "C" void kernel_launch(void* const* d_in, const int* in_sizes, int n_in,
                              void* d_out, int out_size)
{
    (void)in_sizes; (void)n_in; (void)out_size;
    const float* x  = (const float*)d_in[0];
    const float* Wq = (const float*)d_in[1];
    const float* Wk = (const float*)d_in[2];
    const float* Wv = (const float*)d_in[3];
    float* out = (float*)d_out;

    convert_w2_kernel<<<96, 256, 64*133*4>>>(Wq, Wk, Wv);

    cudaFuncSetAttribute(proj_hmma5_kernel,
                         cudaFuncAttributeMaxDynamicSharedMemorySize, PX_SMEM);
    proj_hmma5_kernel<<<148, 256, PX_SMEM>>>(x);

    cudaFuncSetAttribute(flash6_kernel,
                         cudaFuncAttributeMaxDynamicSharedMemorySize, FSMEM);
    flash6_kernel<<<dim3(16, B_), 256, FSMEM>>>(out);
}